// round 9
// baseline (speedup 1.0000x reference)
#include <cuda_runtime.h>

#define B 8
#define S 64
#define V 50257
#define P 200
#define NCHUNK 7
#define THREADS 256
#define INV_T  (1.0f/0.6f)
#define PEN    1.2f
#define INV_PEN (1.0f/1.2f)
#define BSTRIDE  ((size_t)S * V)

__device__ float g_pl[S * NCHUNK * B];   // penalty-free partial sums
__device__ float g_corr[S * B];          // sparse penalty corrections to the sums

// Aligned vector range for (s, chunk c): v = a + 4g gives 16B-aligned addresses
// for every batch row b (since (b*S+s)*V ≡ s mod 4 and BSTRIDE % 4 == 0).
__device__ __forceinline__ void chunk_range(int s, int c, int& a, int& G, int& v0, int& v1) {
    a = (4 - (s & 3)) & 3;
    G = (V - a) >> 2;
    const int g0 = (int)(((long long)c * G) / NCHUNK);
    const int g1 = (int)(((long long)(c + 1) * G) / NCHUNK);
    v0 = a + 4 * g0;
    v1 = a + 4 * g1;
}

// ---------------- k_stats: penalty-free sum of exp(x/T), 2 batch rows per CTA.
__global__ __launch_bounds__(THREADS, 6) void k_stats(const float* __restrict__ logits) {
    const int c = blockIdx.x % NCHUNK;
    const int t = blockIdx.x / NCHUNK;
    const int b0 = (t & 3) * 2;
    const int s = t >> 2;
    int a, G, v0, v1;
    chunk_range(s, c, a, G, v0, v1);

    const float* base0 = logits + ((size_t)b0 * S + s) * V;
    const float* base1 = base0 + BSTRIDE;

    float sum0 = 0.0f, sum1 = 0.0f;
    for (int v = v0 + 4 * (int)threadIdx.x; v < v1; v += 4 * THREADS) {
        const float4 x0 = *(const float4*)(base0 + v);
        const float4 x1 = *(const float4*)(base1 + v);
        sum0 += __expf(x0.x * INV_T) + __expf(x0.y * INV_T)
              + __expf(x0.z * INV_T) + __expf(x0.w * INV_T);
        sum1 += __expf(x1.x * INV_T) + __expf(x1.y * INV_T)
              + __expf(x1.z * INV_T) + __expf(x1.w * INV_T);
    }
    if (c == 0) {                         // unaligned head/tail scalars (<=6)
        const int tail0 = a + 4 * G;
        const int cnt = a + (V - tail0);
        if ((int)threadIdx.x < cnt) {
            const int v = ((int)threadIdx.x < a) ? (int)threadIdx.x
                                                 : tail0 + ((int)threadIdx.x - a);
            sum0 += __expf(base0[v] * INV_T);
            sum1 += __expf(base1[v] * INV_T);
        }
    }

#pragma unroll
    for (int off = 16; off; off >>= 1) {
        sum0 += __shfl_xor_sync(0xffffffffu, sum0, off);
        sum1 += __shfl_xor_sync(0xffffffffu, sum1, off);
    }
    __shared__ float s0[THREADS / 32], s1[THREADS / 32];
    const int warp = threadIdx.x >> 5;
    if ((threadIdx.x & 31) == 0) { s0[warp] = sum0; s1[warp] = sum1; }
    __syncthreads();
    if (threadIdx.x == 0) {
        float L0 = 0.0f, L1 = 0.0f;
#pragma unroll
        for (int w = 0; w < THREADS / 32; w++) { L0 += s0[w]; L1 += s1[w]; }
        g_pl[(s * NCHUNK + c) * B + b0] = L0;
        g_pl[(s * NCHUNK + c) * B + b0 + 1] = L1;
    }
}

// ---------------- k_corr: per-sequence sparse sum corrections (dedup'd tokens).
__global__ __launch_bounds__(256) void k_corr(const float* __restrict__ logits,
                                              const int* __restrict__ prev) {
    const int s = blockIdx.x;
    __shared__ int sprev[P];
    __shared__ float acc[256][B];
    const int tid = threadIdx.x;
    if (tid < P) sprev[tid] = prev[s * P + tid];
    __syncthreads();

    float d[B];
#pragma unroll
    for (int b = 0; b < B; b++) d[b] = 0.0f;
    if (tid < P) {
        const int tok = sprev[tid];
        bool uniq = true;
        for (int j = 0; j < tid; j++) uniq &= (sprev[j] != tok);
        if (uniq) {
            float x[B];
            bool allneg = true;
#pragma unroll
            for (int b = 0; b < B; b++) {
                x[b] = logits[((size_t)b * S + s) * V + tok];
                allneg = allneg && (x[b] < 0.0f);
            }
            const float fac = (allneg ? PEN : INV_PEN) * INV_T;
#pragma unroll
            for (int b = 0; b < B; b++)
                d[b] = __expf(x[b] * fac) - __expf(x[b] * INV_T);
        }
    }
#pragma unroll
    for (int b = 0; b < B; b++) acc[tid][b] = d[b];
    __syncthreads();
    for (int off = 128; off; off >>= 1) {
        if (tid < off) {
#pragma unroll
            for (int b = 0; b < B; b++) acc[tid][b] += acc[tid + off][b];
        }
        __syncthreads();
    }
    if (tid < B) g_corr[s * B + tid] = acc[0][tid];
}

// ---------------- k_passC: penalty-free normalize + write (streaming stores).
__global__ __launch_bounds__(THREADS, 6) void k_passC(const float* __restrict__ logits,
                                                      float* __restrict__ out) {
    const int c = blockIdx.x % NCHUNK;
    const int t = blockIdx.x / NCHUNK;
    const int b0 = (t & 3) * 2;
    const int s = t >> 2;
    int a, G, v0, v1;
    chunk_range(s, c, a, G, v0, v1);

    __shared__ float sR[2];
    if (threadIdx.x < 2) {
        const int b = b0 + (int)threadIdx.x;
        float L = g_corr[s * B + b];
#pragma unroll
        for (int cc = 0; cc < NCHUNK; cc++) L += g_pl[(s * NCHUNK + cc) * B + b];
        sR[threadIdx.x] = 1.0f / L;
    }
    __syncthreads();
    const float R0 = sR[0], R1 = sR[1];

    const float* base0 = logits + ((size_t)b0 * S + s) * V;
    const float* base1 = base0 + BSTRIDE;
    float* obase0 = out + ((size_t)b0 * S + s) * V;
    float* obase1 = obase0 + BSTRIDE;

    for (int v = v0 + 4 * (int)threadIdx.x; v < v1; v += 4 * THREADS) {
        const float4 x0 = *(const float4*)(base0 + v);
        const float4 x1 = *(const float4*)(base1 + v);
        float4 o0, o1;
        o0.x = __expf(x0.x * INV_T) * R0;  o0.y = __expf(x0.y * INV_T) * R0;
        o0.z = __expf(x0.z * INV_T) * R0;  o0.w = __expf(x0.w * INV_T) * R0;
        o1.x = __expf(x1.x * INV_T) * R1;  o1.y = __expf(x1.y * INV_T) * R1;
        o1.z = __expf(x1.z * INV_T) * R1;  o1.w = __expf(x1.w * INV_T) * R1;
        __stcs((float4*)(obase0 + v), o0);
        __stcs((float4*)(obase1 + v), o1);
    }
    if (c == 0) {
        const int tail0 = a + 4 * G;
        const int cnt = a + (V - tail0);
        if ((int)threadIdx.x < cnt) {
            const int v = ((int)threadIdx.x < a) ? (int)threadIdx.x
                                                 : tail0 + ((int)threadIdx.x - a);
            obase0[v] = __expf(base0[v] * INV_T) * R0;
            obase1[v] = __expf(base1[v] * INV_T) * R1;
        }
    }
}

// ---------------- k_fix: overwrite the masked positions with penalized values.
__global__ __launch_bounds__(256) void k_fix(const float* __restrict__ logits,
                                             const int* __restrict__ prev,
                                             float* __restrict__ out) {
    const int s = blockIdx.x;
    __shared__ int sprev[P];
    __shared__ float sR[B];
    const int tid = threadIdx.x;
    if (tid < P) sprev[tid] = prev[s * P + tid];
    if (tid < B) {
        float L = g_corr[s * B + tid];
#pragma unroll
        for (int cc = 0; cc < NCHUNK; cc++) L += g_pl[(s * NCHUNK + cc) * B + tid];
        sR[tid] = 1.0f / L;
    }
    __syncthreads();

    if (tid < P) {
        const int tok = sprev[tid];
        bool uniq = true;
        for (int j = 0; j < tid; j++) uniq &= (sprev[j] != tok);
        if (uniq) {
            float x[B];
            bool allneg = true;
#pragma unroll
            for (int b = 0; b < B; b++) {
                x[b] = logits[((size_t)b * S + s) * V + tok];
                allneg = allneg && (x[b] < 0.0f);
            }
            const float fac = (allneg ? PEN : INV_PEN) * INV_T;
#pragma unroll
            for (int b = 0; b < B; b++)
                out[((size_t)b * S + s) * V + tok] = __expf(x[b] * fac) * sR[b];
        }
    }
}

extern "C" void kernel_launch(void* const* d_in, const int* in_sizes, int n_in,
                              void* d_out, int out_size) {
    const float* logits = (const float*)d_in[0];
    const int* prev = (const int*)d_in[1];
    float* out = (float*)d_out;
    (void)in_sizes; (void)n_in; (void)out_size;

    k_stats<<<S * NCHUNK * 4, THREADS>>>(logits);
    k_corr<<<S, 256>>>(logits, prev);
    k_passC<<<S * NCHUNK * 4, THREADS>>>(logits, out);
    k_fix<<<S, 256>>>(logits, prev, out);
}

// round 10
// speedup vs baseline: 1.0864x; 1.0864x over previous
#include <cuda_runtime.h>

#define B 8
#define S 64
#define V 50257
#define P 200
#define NCHUNK 7
#define THREADS 256
#define MWORDS 232            // max chunk span ~7184 floats -> 225 words, padded
#define INV_T  (1.0f/0.6f)
#define PEN    1.2f
#define INV_PEN (1.0f/1.2f)
#define BSTRIDE  ((size_t)S * V)

__device__ float g_pl[S * NCHUNK * B];   // partial sums (penalty included)

// Aligned vector range for (s, chunk c): v = a + 4g is 16B-aligned for every
// batch row (since (b*S+s)*V ≡ s mod 4 and BSTRIDE % 4 == 0).
__device__ __forceinline__ void chunk_range(int s, int c, int& a, int& G, int& v0, int& v1) {
    a = (4 - (s & 3)) & 3;
    G = (V - a) >> 2;
    const int g0 = (int)(((long long)c * G) / NCHUNK);
    const int g1 = (int)(((long long)(c + 1) * G) / NCHUNK);
    v0 = a + 4 * g0;
    v1 = a + 4 * g1;
}

__device__ __forceinline__ void build_mask(unsigned* smask, int* sprev,
                                           const int* __restrict__ prev,
                                           int s, int v0, int v1) {
    for (int i = threadIdx.x; i < MWORDS; i += THREADS) smask[i] = 0u;
    __syncthreads();
    for (int t = threadIdx.x; t < P; t += THREADS) {
        const int tok = prev[s * P + t];
        sprev[t] = tok;
        if (tok >= v0 && tok < v1) {
            const int r = tok - v0;
            atomicOr(&smask[r >> 5], 1u << (r & 31));
        }
    }
}

// all_neg over all 8 batch rows at position v (rare path; ~0.4% of elements).
__device__ __forceinline__ float penal_fac(const float* __restrict__ logits,
                                           int s, int v) {
    bool allneg = true;
#pragma unroll
    for (int b = 0; b < B; b++)
        allneg = allneg && (logits[((size_t)b * S + s) * V + v] < 0.0f);
    return (allneg ? PEN : INV_PEN) * INV_T;
}

// ---------------- Pass A: sums of exp(penalized/T) for 2 batch rows per CTA.
__global__ __launch_bounds__(THREADS, 6) void k_stats(const float* __restrict__ logits,
                                                      const int* __restrict__ prev) {
    const int c = blockIdx.x % NCHUNK;
    const int t = blockIdx.x / NCHUNK;
    const int b0 = (t & 3) * 2;
    const int s = t >> 2;
    int a, G, v0, v1;
    chunk_range(s, c, a, G, v0, v1);

    __shared__ unsigned smask[MWORDS];
    __shared__ int sprev[P];
    build_mask(smask, sprev, prev, s, v0, v1);
    __syncthreads();

    const float* base0 = logits + ((size_t)b0 * S + s) * V;
    const float* base1 = base0 + BSTRIDE;

    float sum0 = 0.0f, sum1 = 0.0f;
    for (int v = v0 + 4 * (int)threadIdx.x; v < v1; v += 4 * THREADS) {
        const int r = v - v0;
        const unsigned bits4 = (smask[r >> 5] >> (r & 31)) & 0xFu;
        const float4 x0 = *(const float4*)(base0 + v);
        const float4 x1 = *(const float4*)(base1 + v);
        if (bits4 == 0u) {
            sum0 += __expf(x0.x * INV_T) + __expf(x0.y * INV_T)
                  + __expf(x0.z * INV_T) + __expf(x0.w * INV_T);
            sum1 += __expf(x1.x * INV_T) + __expf(x1.y * INV_T)
                  + __expf(x1.z * INV_T) + __expf(x1.w * INV_T);
        } else {
            const float a0[4] = {x0.x, x0.y, x0.z, x0.w};
            const float a1[4] = {x1.x, x1.y, x1.z, x1.w};
#pragma unroll
            for (int j = 0; j < 4; j++) {
                const float fac = ((bits4 >> j) & 1u) ? penal_fac(logits, s, v + j)
                                                      : INV_T;
                sum0 += __expf(a0[j] * fac);
                sum1 += __expf(a1[j] * fac);
            }
        }
    }

    if (c == 0) {                         // unaligned head/tail scalars (<=6)
        const int tail0 = a + 4 * G;
        const int cnt = a + (V - tail0);
        if ((int)threadIdx.x < cnt) {
            const int v = ((int)threadIdx.x < a) ? (int)threadIdx.x
                                                 : tail0 + ((int)threadIdx.x - a);
            bool hit = false;
            for (int p = 0; p < P; p++) hit |= (sprev[p] == v);
            const float fac = hit ? penal_fac(logits, s, v) : INV_T;
            sum0 += __expf(base0[v] * fac);
            sum1 += __expf(base1[v] * fac);
        }
    }

#pragma unroll
    for (int off = 16; off; off >>= 1) {
        sum0 += __shfl_xor_sync(0xffffffffu, sum0, off);
        sum1 += __shfl_xor_sync(0xffffffffu, sum1, off);
    }
    __shared__ float s0[THREADS / 32], s1[THREADS / 32];
    const int warp = threadIdx.x >> 5;
    if ((threadIdx.x & 31) == 0) { s0[warp] = sum0; s1[warp] = sum1; }
    __syncthreads();
    if (threadIdx.x == 0) {
        float L0 = 0.0f, L1 = 0.0f;
#pragma unroll
        for (int w = 0; w < THREADS / 32; w++) { L0 += s0[w]; L1 += s1[w]; }
        g_pl[(s * NCHUNK + c) * B + b0] = L0;
        g_pl[(s * NCHUNK + c) * B + b0 + 1] = L1;
    }
}

// ---------------- Pass C: normalize + write (penalty applied inline).
__global__ __launch_bounds__(THREADS, 6) void k_passC(const float* __restrict__ logits,
                                                      const int* __restrict__ prev,
                                                      float* __restrict__ out) {
    const int c = blockIdx.x % NCHUNK;
    const int t = blockIdx.x / NCHUNK;
    const int b0 = (t & 3) * 2;
    const int s = t >> 2;
    int a, G, v0, v1;
    chunk_range(s, c, a, G, v0, v1);

    __shared__ unsigned smask[MWORDS];
    __shared__ int sprev[P];
    __shared__ float sR[2];
    build_mask(smask, sprev, prev, s, v0, v1);
    if (threadIdx.x < 2) {
        const int b = b0 + (int)threadIdx.x;
        float L = 0.0f;
#pragma unroll
        for (int cc = 0; cc < NCHUNK; cc++) L += g_pl[(s * NCHUNK + cc) * B + b];
        sR[threadIdx.x] = 1.0f / L;
    }
    __syncthreads();
    const float R0 = sR[0], R1 = sR[1];

    const float* base0 = logits + ((size_t)b0 * S + s) * V;
    const float* base1 = base0 + BSTRIDE;
    float* obase0 = out + ((size_t)b0 * S + s) * V;
    float* obase1 = obase0 + BSTRIDE;

    for (int v = v0 + 4 * (int)threadIdx.x; v < v1; v += 4 * THREADS) {
        const int r = v - v0;
        const unsigned bits4 = (smask[r >> 5] >> (r & 31)) & 0xFu;
        const float4 x0 = __ldcs((const float4*)(base0 + v));
        const float4 x1 = __ldcs((const float4*)(base1 + v));
        float4 o0, o1;
        if (bits4 == 0u) {
            o0.x = __expf(x0.x * INV_T) * R0;  o0.y = __expf(x0.y * INV_T) * R0;
            o0.z = __expf(x0.z * INV_T) * R0;  o0.w = __expf(x0.w * INV_T) * R0;
            o1.x = __expf(x1.x * INV_T) * R1;  o1.y = __expf(x1.y * INV_T) * R1;
            o1.z = __expf(x1.z * INV_T) * R1;  o1.w = __expf(x1.w * INV_T) * R1;
        } else {
            const float a0[4] = {x0.x, x0.y, x0.z, x0.w};
            const float a1[4] = {x1.x, x1.y, x1.z, x1.w};
            float r0[4], r1[4];
#pragma unroll
            for (int j = 0; j < 4; j++) {
                const float fac = ((bits4 >> j) & 1u) ? penal_fac(logits, s, v + j)
                                                      : INV_T;
                r0[j] = __expf(a0[j] * fac) * R0;
                r1[j] = __expf(a1[j] * fac) * R1;
            }
            o0.x = r0[0]; o0.y = r0[1]; o0.z = r0[2]; o0.w = r0[3];
            o1.x = r1[0]; o1.y = r1[1]; o1.z = r1[2]; o1.w = r1[3];
        }
        __stcs((float4*)(obase0 + v), o0);
        __stcs((float4*)(obase1 + v), o1);
    }

    if (c == 0) {
        const int tail0 = a + 4 * G;
        const int cnt = a + (V - tail0);
        if ((int)threadIdx.x < cnt) {
            const int v = ((int)threadIdx.x < a) ? (int)threadIdx.x
                                                 : tail0 + ((int)threadIdx.x - a);
            bool hit = false;
            for (int p = 0; p < P; p++) hit |= (sprev[p] == v);
            const float fac = hit ? penal_fac(logits, s, v) : INV_T;
            obase0[v] = __expf(base0[v] * fac) * R0;
            obase1[v] = __expf(base1[v] * fac) * R1;
        }
    }
}

extern "C" void kernel_launch(void* const* d_in, const int* in_sizes, int n_in,
                              void* d_out, int out_size) {
    const float* logits = (const float*)d_in[0];
    const int* prev = (const int*)d_in[1];
    float* out = (float*)d_out;
    (void)in_sizes; (void)n_in; (void)out_size;

    k_stats<<<S * 4 * NCHUNK, THREADS>>>(logits, prev);
    k_passC<<<S * 4 * NCHUNK, THREADS>>>(logits, prev, out);
}